// round 9
// baseline (speedup 1.0000x reference)
#include <cuda_runtime.h>
#include <math.h>
#include <stdint.h>

#define NB 48
#define NC 3
#define HH 256
#define WW 256

#define TW 128
#define TH 32
#define HT (TH + 10)       // 42 intermediate rows
#define WTIN (TW + 10)     // 138 input cols used
#define WPAD 144           // padded row stride (floats)
#define HW 32              // quarter-tile width for phase 1/2
#define NPASS (TW / HW)    // 4
#define GX (WW / TW)       // 2
#define GY (HH / TH)       // 8
#define NIMG (NB * NC)     // 144
#define NBLK (GX * GY * NIMG) // 2304

#define NPERSIST 444       // 148 SMs x 3 CTAs: one wave

#define C1S 1e-4f
#define C2S 9e-4f

// ---- packed f32x2 helpers (used ONLY in phase 2, where data is already
// 64-bit in smem; phase-1 scalar->pair packing was shown to be a net loss) ----
#define PACK2(d, lo, hi) \
    asm("mov.b64 %0, {%1, %2};" : "=l"(d) : "f"(lo), "f"(hi))
#define UNPACK2(lo, hi, s) \
    asm("mov.b64 {%0, %1}, %2;" : "=f"(lo), "=f"(hi) : "l"(s))
#define MUL2(d, a, b) \
    asm("mul.rn.f32x2 %0, %1, %2;" : "=l"(d) : "l"(a), "l"(b))
#define ADD2(d, a, b) \
    asm("add.rn.f32x2 %0, %1, %2;" : "=l"(d) : "l"(a), "l"(b))
#define FMA2(d, a, b, c) \
    asm("fma.rn.f32x2 %0, %1, %2, %3;" : "=l"(d) : "l"(a), "l"(b), "l"(c))

// 1D Gaussian (k=11, sigma=1.5) — compile-time constants -> FFMA-imm.
__device__ static constexpr float GK[11] = {
    0.00102840f, 0.00759880f, 0.03600060f, 0.10936270f, 0.21300441f,
    0.26601031f,
    0.21300441f, 0.10936270f, 0.03600060f, 0.00759880f, 0.00102840f
};

__device__ float g_edge[NB * HH * 24];   // per-(n,row,edge) crossing-x
__device__ float g_bbox[NB * 8];         // per-n: bx0[3], bx1[3]
__device__ float g_part[NBLK];
__device__ unsigned g_ticket;            // dynamic tile counter

// ---------------------------------------------------------------------------
// Kernel A: per-(n,row,edge) crossing table + x-bboxes. Also resets ticket.
// ---------------------------------------------------------------------------
__global__ void __launch_bounds__(256) edge_kernel(const float* __restrict__ lm)
{
    __shared__ float lx[24], ly[24];
    __shared__ float bx0[3], bx1[3], by0[3], by1[3];

    const int n = blockIdx.x;
    const int tid = threadIdx.x;

    if (n == 0 && tid == 0) g_ticket = 0u;

    if (tid < 24) {
        lx[tid] = lm[(n * 68 + 36 + tid) * 2 + 0];
        ly[tid] = lm[(n * 68 + 36 + tid) * 2 + 1];
    }
    __syncthreads();
    if (tid < 3) {
        const int b = tid * 6;
        const int np = (tid == 2) ? 12 : 6;
        float mnx = lx[b], mxx = lx[b], mny = ly[b], mxy = ly[b];
        for (int i = 1; i < np; i++) {
            mnx = fminf(mnx, lx[b + i]); mxx = fmaxf(mxx, lx[b + i]);
            mny = fminf(mny, ly[b + i]); mxy = fmaxf(mxy, ly[b + i]);
        }
        float fx0 = floorf(mnx), fx1 = floorf(mxx);
        float fy0 = floorf(mny), fy1 = floorf(mxy);
        const bool valid = (fx0 >= 0.f && fy0 >= 0.f &&
                            fx1 < (float)WW && fy1 < (float)HH);
        if (!valid) { fx0 = 1e30f; fx1 = -1e30f; fy0 = 1e30f; fy1 = -1e30f; }
        bx0[tid] = fx0; bx1[tid] = fx1; by0[tid] = fy0; by1[tid] = fy1;
    }
    __syncthreads();
    if (tid < 3) {
        g_bbox[n * 8 + tid]     = bx0[tid];
        g_bbox[n * 8 + 4 + tid] = bx1[tid];
    }

    for (int u = tid; u < HH * 24; u += 256) {
        const int row = u / 24;
        const int e = u - row * 24;
        const int p3 = (e < 6) ? 0 : (e < 12) ? 1 : 2;
        const int base = p3 * 6;
        const int np = (p3 == 2) ? 12 : 6;
        const float Y = (float)row;
        const float x1 = lx[e], y1 = ly[e];
        const int e2 = base + ((e - base + 1) % np);
        const float x2 = lx[e2], y2 = ly[e2];
        const bool strad = (y1 > Y) != (y2 > Y);
        const bool rowok = (Y >= by0[p3]) && (Y < by1[p3]);
        const float xi = (x2 - x1) * (Y - y1) / (y2 - y1 + 1e-6f) + x1;
        g_edge[(size_t)n * HH * 24 + u] = (strad && rowok) ? xi : -1e30f;
    }
}

// Padding no-ops so the profiled launch stays main_kernel.
__global__ void nop_kernel() {}

// ---------------------------------------------------------------------------
// Main kernel: persistent CTAs; scalar phase 1, packed-f32x2 phase 2.
// ---------------------------------------------------------------------------
__global__ void __launch_bounds__(256, 3)
main_kernel(const float* __restrict__ pred, const float* __restrict__ targ)
{
    extern __shared__ float sm[];
    float* s_p  = sm;                          // HT*WPAD = 6048
    float* s_t  = sm + HT * WPAD;              // 6048
    float* s_h  = sm + 2 * HT * WPAD;          // 4*HT*HW = 5376
    float* s_sx = s_h + 4 * HT * HW;           // TH*24 = 768
    float* s_r  = s_sx + TH * 24;              // 8

    __shared__ float s_bx0[3], s_bx1[3];
    __shared__ unsigned s_tile;

    const int tid = threadIdx.x;
    const int warp = tid >> 5, lane = tid & 31;

    for (;;) {
        if (tid == 0) s_tile = atomicAdd(&g_ticket, 1u);
        __syncthreads();
        const unsigned tile = s_tile;
        if (tile >= NBLK) break;

        const int bx = tile & (GX - 1);
        const int by = (tile >> 1) & (GY - 1);
        const int img = tile >> 4;
        const int c0 = bx * TW;
        const int r0 = by * TH;
        const int n = img / NC;

        const float* __restrict__ P = pred + (size_t)img * (HH * WW);
        const float* __restrict__ T = targ + (size_t)img * (HH * WW);

        if (tid < 3) {
            s_bx0[tid] = g_bbox[n * 8 + tid];
            s_bx1[tid] = g_bbox[n * 8 + 4 + tid];
        }
        for (int u = tid; u < TH * 24; u += 256)
            s_sx[u] = g_edge[(size_t)n * HH * 24 + r0 * 24 + u];

        // ---- Loop A: clean tile load with zero halo (no integer division) ----
        for (int i = warp; i < HT; i += 8) {
            const int gr = r0 - 5 + i;
            const bool rok = (unsigned)gr < HH;
            const float* Pr = P + gr * WW;
            const float* Tr = T + gr * WW;
            for (int j = lane; j < WPAD; j += 32) {
                const int gc = c0 - 5 + j;
                float pv = 0.f, tv = 0.f;
                if (j < WTIN && rok && (unsigned)gc < WW) {
                    pv = Pr[gc];
                    tv = Tr[gc];
                }
                s_p[i * WPAD + j] = pv;
                s_t[i * WPAD + j] = tv;
            }
        }
        __syncthreads();

        float acc = 0.f;

        // ---- Loop B: weighted L1, warp-uniform polygon-region skip ----
        for (int idx = tid; idx < TH * TW; idx += 256) {
            const int r = idx >> 7;
            const int c = idx & 127;
            const int so = (r + 5) * WPAD + c + 5;
            const float ad = fabsf(s_p[so] - s_t[so]);
            const float X = (float)(c0 + c);
            const bool in0 = (X >= s_bx0[0]) && (X < s_bx1[0]);
            const bool in1 = (X >= s_bx0[1]) && (X < s_bx1[1]);
            const bool in2 = (X >= s_bx0[2]) && (X < s_bx1[2]);
            if (__any_sync(0xffffffffu, in0 | in1 | in2)) {
                const float* sxr = s_sx + r * 24;
                float w = 1.f;
                if (in0) {
                    int par = (X < sxr[0]) ^ (X < sxr[1]) ^ (X < sxr[2]) ^
                              (X < sxr[3]) ^ (X < sxr[4]) ^ (X < sxr[5]);
                    if (par) w += 3.f;
                }
                if (in1) {
                    int par = (X < sxr[6]) ^ (X < sxr[7]) ^ (X < sxr[8]) ^
                              (X < sxr[9]) ^ (X < sxr[10]) ^ (X < sxr[11]);
                    if (par) w += 3.f;
                }
                if (in2) {
                    int par = (X < sxr[12]) ^ (X < sxr[13]) ^ (X < sxr[14]) ^
                              (X < sxr[15]) ^ (X < sxr[16]) ^ (X < sxr[17]) ^
                              (X < sxr[18]) ^ (X < sxr[19]) ^ (X < sxr[20]) ^
                              (X < sxr[21]) ^ (X < sxr[22]) ^ (X < sxr[23]);
                    if (par) w += 2.f;
                }
                acc += (10.f + 5.f * w) * ad;
            } else {
                acc += 15.f * ad;
            }
        }

        // ---- Phases 1+2 over four 32-col quarters ----
        #pragma unroll 1
        for (int h = 0; h < NPASS; h++) {
            __syncthreads();

            // Phase 1 (scalar): horizontal 11-tap conv of 4 fields
            for (int t2 = tid; t2 < HT * (HW / 4); t2 += 256) {
                const int i = t2 >> 3;
                const int q = t2 & 7;
                const int cb = h * HW + 4 * q;
                const float4* rp = (const float4*)(s_p + i * WPAD + cb);
                const float4* rt = (const float4*)(s_t + i * WPAD + cb);
                float p[16], t[16];
                float4 v;
                v = rp[0]; p[0]=v.x; p[1]=v.y; p[2]=v.z; p[3]=v.w;
                v = rp[1]; p[4]=v.x; p[5]=v.y; p[6]=v.z; p[7]=v.w;
                v = rp[2]; p[8]=v.x; p[9]=v.y; p[10]=v.z; p[11]=v.w;
                v = rp[3]; p[12]=v.x; p[13]=v.y; p[14]=v.z; p[15]=v.w;
                v = rt[0]; t[0]=v.x; t[1]=v.y; t[2]=v.z; t[3]=v.w;
                v = rt[1]; t[4]=v.x; t[5]=v.y; t[6]=v.z; t[7]=v.w;
                v = rt[2]; t[8]=v.x; t[9]=v.y; t[10]=v.z; t[11]=v.w;
                v = rt[3]; t[12]=v.x; t[13]=v.y; t[14]=v.z; t[15]=v.w;

                float s2[14], pt[14];
                #pragma unroll
                for (int u = 0; u < 14; u++) {
                    s2[u] = fmaf(p[u], p[u], t[u] * t[u]);
                    pt[u] = p[u] * t[u];
                }
                float hx[4], hy[4], hs[4], hxy[4];
                #pragma unroll
                for (int k = 0; k < 4; k++) {
                    float a = 0.f, b = 0.f, c = 0.f, e = 0.f;
                    #pragma unroll
                    for (int j = 0; j < 11; j++) {
                        const float g = GK[j];
                        a += g * p[k + j];
                        b += g * t[k + j];
                        c += g * s2[k + j];
                        e += g * pt[k + j];
                    }
                    hx[k] = a; hy[k] = b; hs[k] = c; hxy[k] = e;
                }
                const int off = i * HW + 4 * q;
                *(float4*)(s_h + 0 * HT * HW + off) = make_float4(hx[0], hx[1], hx[2], hx[3]);
                *(float4*)(s_h + 1 * HT * HW + off) = make_float4(hy[0], hy[1], hy[2], hy[3]);
                *(float4*)(s_h + 2 * HT * HW + off) = make_float4(hs[0], hs[1], hs[2], hs[3]);
                *(float4*)(s_h + 3 * HT * HW + off) = make_float4(hxy[0], hxy[1], hxy[2], hxy[3]);
            }
            __syncthreads();

            // Phase 2 (packed f32x2): 2 rows x 2 cols per thread
            {
                uint64_t g2[11];
                #pragma unroll
                for (int j = 0; j < 11; j++) PACK2(g2[j], GK[j], GK[j]);
                uint64_t two2, c12, c22, eps2, neg1;
                PACK2(two2, 2.0f, 2.0f);
                PACK2(c12, C1S, C1S);
                PACK2(c22, C2S, C2S);
                PACK2(eps2, 1e-8f, 1e-8f);
                PACK2(neg1, -1.0f, -1.0f);

                const int cpair = tid & 15;      // 16 col-pairs
                const int rg = tid >> 4;         // 16 row groups (2 rows each)

                uint64_t Ax[2] = {0ull, 0ull}, Ay[2] = {0ull, 0ull};
                uint64_t As[2] = {0ull, 0ull}, Axy[2] = {0ull, 0ull};

                #pragma unroll
                for (int rr = 0; rr < 12; rr++) {
                    const int off = (rg * 2 + rr) * HW + 2 * cpair;
                    const uint64_t vx  = *(const uint64_t*)(s_h + 0 * HT * HW + off);
                    const uint64_t vy  = *(const uint64_t*)(s_h + 1 * HT * HW + off);
                    const uint64_t vs  = *(const uint64_t*)(s_h + 2 * HT * HW + off);
                    const uint64_t vxy = *(const uint64_t*)(s_h + 3 * HT * HW + off);
                    #pragma unroll
                    for (int k = 0; k < 2; k++) {
                        const int j = rr - k;
                        if (j >= 0 && j < 11) {
                            FMA2(Ax[k],  g2[j], vx,  Ax[k]);
                            FMA2(Ay[k],  g2[j], vy,  Ay[k]);
                            FMA2(As[k],  g2[j], vs,  As[k]);
                            FMA2(Axy[k], g2[j], vxy, Axy[k]);
                        }
                    }
                }

                float sds = 0.f;
                #pragma unroll
                for (int k = 0; k < 2; k++) {
                    uint64_t t1, mx2my2, sxsy, mxmy, sxy;
                    uint64_t num1, num2, den1, den2, num, den;
                    MUL2(t1, Ay[k], Ay[k]);
                    FMA2(mx2my2, Ax[k], Ax[k], t1);       // mx^2 + my^2
                    FMA2(sxsy, mx2my2, neg1, As[k]);      // sigma_x + sigma_y
                    MUL2(mxmy, Ax[k], Ay[k]);
                    FMA2(sxy, mxmy, neg1, Axy[k]);        // sigma_xy
                    FMA2(num1, mxmy, two2, c12);
                    FMA2(num2, sxy, two2, c22);
                    ADD2(den1, mx2my2, c12);
                    ADD2(den2, sxsy, c22);
                    MUL2(num, num1, num2);
                    MUL2(den, den1, den2);
                    ADD2(den, den, eps2);
                    float nlo, nhi, dlo, dhi;
                    UNPACK2(nlo, nhi, num);
                    UNPACK2(dlo, dhi, den);
                    sds += (1.f - __fdividef(nlo, dlo));
                    sds += (1.f - __fdividef(nhi, dhi));
                }
                acc += 5.f * sds;   // 10 * (1-ssim)/2
            }
        }

        // ---- deterministic per-tile reduction ----
        #pragma unroll
        for (int o = 16; o > 0; o >>= 1)
            acc += __shfl_down_sync(0xffffffffu, acc, o);
        __syncthreads();
        if (lane == 0) s_r[warp] = acc;
        __syncthreads();
        if (warp == 0) {
            float v = (lane < 8) ? s_r[lane] : 0.f;
            #pragma unroll
            for (int o = 4; o > 0; o >>= 1)
                v += __shfl_down_sync(0xffffffffu, v, o);
            if (lane == 0) g_part[tile] = v;
        }
        __syncthreads();
    }
}

// ---------------------------------------------------------------------------
// Single deterministic reduction: 2304 -> scalar (double precision).
// ---------------------------------------------------------------------------
__global__ void __launch_bounds__(256) reduce_kernel(float* __restrict__ out)
{
    __shared__ double sd[256];
    const int tid = threadIdx.x;
    double s = 0.0;
    for (int i = tid; i < NBLK; i += 256) s += (double)g_part[i];
    sd[tid] = s;
    __syncthreads();
    for (int st = 128; st > 0; st >>= 1) {
        if (tid < st) sd[tid] += sd[tid + st];
        __syncthreads();
    }
    if (tid == 0) {
        out[0] = (float)(sd[0] / ((double)NB * (double)NC * (double)HH * (double)WW));
    }
}

extern "C" void kernel_launch(void* const* d_in, const int* in_sizes, int n_in,
                              void* d_out, int out_size)
{
    const float* pred = (const float*)d_in[0];
    const float* targ = (const float*)d_in[1];
    const float* lm   = (const float*)d_in[2];
    float* out = (float*)d_out;
    (void)in_sizes; (void)n_in; (void)out_size;

    edge_kernel<<<NB, 256>>>(lm);
    nop_kernel<<<1, 32>>>();
    nop_kernel<<<1, 32>>>();

    const size_t smem = (size_t)(2 * HT * WPAD + 4 * HT * HW + TH * 24 + 8)
                        * sizeof(float);
    cudaFuncSetAttribute(main_kernel,
                         cudaFuncAttributeMaxDynamicSharedMemorySize, (int)smem);
    main_kernel<<<NPERSIST, 256, smem>>>(pred, targ);

    reduce_kernel<<<1, 256>>>(out);
}

// round 10
// speedup vs baseline: 1.0246x; 1.0246x over previous
#include <cuda_runtime.h>
#include <math.h>
#include <stdint.h>

#define NB 48
#define NC 3
#define HH 256
#define WW 256
#define NIMG (NB * NC)            // 144
#define NPIX ((size_t)NIMG * HH * WW)

#define K1_BLOCKS (NIMG * 64)     // 4 rows x 64 quads per 256-thr block
#define K2_BLOCKS (NIMG * 32)     // 8 rows x 256 cols per 256-thr block

#define C1S 1e-4f
#define C2S 9e-4f

// 1D Gaussian (k=11, sigma=1.5) — compile-time constants -> FFMA-imm.
__device__ static constexpr float GK[11] = {
    0.00102840f, 0.00759880f, 0.03600060f, 0.10936270f, 0.21300441f,
    0.26601031f,
    0.21300441f, 0.10936270f, 0.03600060f, 0.00759880f, 0.00102840f
};

__device__ float g_edge[NB * HH * 24];   // per-(n,row,edge) crossing-x
__device__ float g_bbox[NB * 8];         // per-n: bx0[3], bx1[3]
__device__ float4 g_h[NPIX];             // 4 moment fields per pixel (151 MB)
__device__ float g_partA[K1_BLOCKS];
__device__ float g_partB[K2_BLOCKS];

// ---------------------------------------------------------------------------
// Kernel A: per-(n,row,edge) crossing table + x-bboxes.
// ---------------------------------------------------------------------------
__global__ void __launch_bounds__(256) edge_kernel(const float* __restrict__ lm)
{
    __shared__ float lx[24], ly[24];
    __shared__ float bx0[3], bx1[3], by0[3], by1[3];

    const int n = blockIdx.x;
    const int tid = threadIdx.x;

    if (tid < 24) {
        lx[tid] = lm[(n * 68 + 36 + tid) * 2 + 0];
        ly[tid] = lm[(n * 68 + 36 + tid) * 2 + 1];
    }
    __syncthreads();
    if (tid < 3) {
        const int b = tid * 6;
        const int np = (tid == 2) ? 12 : 6;
        float mnx = lx[b], mxx = lx[b], mny = ly[b], mxy = ly[b];
        for (int i = 1; i < np; i++) {
            mnx = fminf(mnx, lx[b + i]); mxx = fmaxf(mxx, lx[b + i]);
            mny = fminf(mny, ly[b + i]); mxy = fmaxf(mxy, ly[b + i]);
        }
        float fx0 = floorf(mnx), fx1 = floorf(mxx);
        float fy0 = floorf(mny), fy1 = floorf(mxy);
        const bool valid = (fx0 >= 0.f && fy0 >= 0.f &&
                            fx1 < (float)WW && fy1 < (float)HH);
        if (!valid) { fx0 = 1e30f; fx1 = -1e30f; fy0 = 1e30f; fy1 = -1e30f; }
        bx0[tid] = fx0; bx1[tid] = fx1; by0[tid] = fy0; by1[tid] = fy1;
    }
    __syncthreads();
    if (tid < 3) {
        g_bbox[n * 8 + tid]     = bx0[tid];
        g_bbox[n * 8 + 4 + tid] = bx1[tid];
    }

    for (int u = tid; u < HH * 24; u += 256) {
        const int row = u / 24;
        const int e = u - row * 24;
        const int p3 = (e < 6) ? 0 : (e < 12) ? 1 : 2;
        const int base = p3 * 6;
        const int np = (p3 == 2) ? 12 : 6;
        const float Y = (float)row;
        const float x1 = lx[e], y1 = ly[e];
        const int e2 = base + ((e - base + 1) % np);
        const float x2 = lx[e2], y2 = ly[e2];
        const bool strad = (y1 > Y) != (y2 > Y);
        const bool rowok = (Y >= by0[p3]) && (Y < by1[p3]);
        const float xi = (x2 - x1) * (Y - y1) / (y2 - y1 + 1e-6f) + x1;
        g_edge[(size_t)n * HH * 24 + u] = (strad && rowok) ? xi : -1e30f;
    }
}

// ---------------------------------------------------------------------------
// Kernel 1: horizontal 11-tap conv of the 4 moment fields + weighted L1.
// One thread = 4 output cols of one row. No smem conv data, no vertical halo,
// no barriers (except the final 1-barrier block reduce).
// ---------------------------------------------------------------------------
__global__ void __launch_bounds__(256, 2)
hconv_kernel(const float* __restrict__ pred, const float* __restrict__ targ)
{
    __shared__ float s_r[8];

    const int tid = threadIdx.x;
    const int warp = tid >> 5, lane = tid & 31;
    const int quad = tid & 63;                 // 64 col-quads
    const int img = blockIdx.x >> 6;
    const int row = ((blockIdx.x & 63) << 2) + (tid >> 6);
    const int n = img / NC;

    const float* __restrict__ P = pred + (size_t)img * (HH * WW) + row * WW;
    const float* __restrict__ T = targ + (size_t)img * (HH * WW) + row * WW;

    // load window: cols [4q-8, 4q+12) — 5 aligned float4s, zero OOB
    const int wb = (quad << 2) - 8;
    float p[20], t[20];
    #pragma unroll
    for (int m = 0; m < 5; m++) {
        const int gc = wb + 4 * m;
        float4 vp = make_float4(0.f, 0.f, 0.f, 0.f);
        float4 vt = make_float4(0.f, 0.f, 0.f, 0.f);
        if ((unsigned)gc < (unsigned)WW) {     // gc % 4 == 0 -> whole quad in range
            vp = *(const float4*)(P + gc);
            vt = *(const float4*)(T + gc);
        }
        p[4*m+0] = vp.x; p[4*m+1] = vp.y; p[4*m+2] = vp.z; p[4*m+3] = vp.w;
        t[4*m+0] = vt.x; t[4*m+1] = vt.y; t[4*m+2] = vt.z; t[4*m+3] = vt.w;
    }

    float s2[14], pt[14];
    #pragma unroll
    for (int u = 0; u < 14; u++) {
        s2[u] = fmaf(p[u+3], p[u+3], t[u+3] * t[u+3]);   // p^2 + t^2
        pt[u] = p[u+3] * t[u+3];
    }

    float4* __restrict__ Hout = g_h + (size_t)img * (HH * WW) + row * WW;
    #pragma unroll
    for (int k = 0; k < 4; k++) {
        float a = 0.f, b = 0.f, c = 0.f, e = 0.f;
        #pragma unroll
        for (int j = 0; j < 11; j++) {
            const float g = GK[j];
            a += g * p[k + j + 3];
            b += g * t[k + j + 3];
            c += g * s2[k + j];
            e += g * pt[k + j];
        }
        Hout[(quad << 2) + k] = make_float4(a, b, c, e);
    }

    // ---- weighted L1 for these 4 pixels ----
    float acc = 0.f;
    const float bxa0 = g_bbox[n * 8 + 0], bxa1 = g_bbox[n * 8 + 4];
    const float bxb0 = g_bbox[n * 8 + 1], bxb1 = g_bbox[n * 8 + 5];
    const float bxc0 = g_bbox[n * 8 + 2], bxc1 = g_bbox[n * 8 + 6];
    const float cf = (float)(quad << 2);       // first col
    const float cl = cf + 3.f;                 // last col
    const bool tin = (bxa0 <= cl && bxa1 > cf) ||
                     (bxb0 <= cl && bxb1 > cf) ||
                     (bxc0 <= cl && bxc1 > cf);
    if (__any_sync(0xffffffffu, tin)) {
        float sx[24];
        const float* __restrict__ E = g_edge + ((size_t)n * HH + row) * 24;
        #pragma unroll
        for (int e2 = 0; e2 < 24; e2++) sx[e2] = E[e2];
        #pragma unroll
        for (int k = 0; k < 4; k++) {
            const float ad = fabsf(p[8 + k] - t[8 + k]);
            const float X = cf + (float)k;
            float w = 1.f;
            if (X >= bxa0 && X < bxa1) {
                int par = (X < sx[0]) ^ (X < sx[1]) ^ (X < sx[2]) ^
                          (X < sx[3]) ^ (X < sx[4]) ^ (X < sx[5]);
                if (par) w += 3.f;
            }
            if (X >= bxb0 && X < bxb1) {
                int par = (X < sx[6]) ^ (X < sx[7]) ^ (X < sx[8]) ^
                          (X < sx[9]) ^ (X < sx[10]) ^ (X < sx[11]);
                if (par) w += 3.f;
            }
            if (X >= bxc0 && X < bxc1) {
                int par = (X < sx[12]) ^ (X < sx[13]) ^ (X < sx[14]) ^
                          (X < sx[15]) ^ (X < sx[16]) ^ (X < sx[17]) ^
                          (X < sx[18]) ^ (X < sx[19]) ^ (X < sx[20]) ^
                          (X < sx[21]) ^ (X < sx[22]) ^ (X < sx[23]);
                if (par) w += 2.f;
            }
            acc += (10.f + 5.f * w) * ad;
        }
    } else {
        #pragma unroll
        for (int k = 0; k < 4; k++)
            acc += 15.f * fabsf(p[8 + k] - t[8 + k]);
    }

    // deterministic block reduce
    #pragma unroll
    for (int o = 16; o > 0; o >>= 1)
        acc += __shfl_down_sync(0xffffffffu, acc, o);
    if (lane == 0) s_r[warp] = acc;
    __syncthreads();
    if (warp == 0) {
        float v = (lane < 8) ? s_r[lane] : 0.f;
        #pragma unroll
        for (int o = 4; o > 0; o >>= 1)
            v += __shfl_down_sync(0xffffffffu, v, o);
        if (lane == 0) g_partA[blockIdx.x] = v;
    }
}

// ---------------------------------------------------------------------------
// Kernel 2: vertical 11-tap conv (register-blocked 8 rows / thread) + SSIM.
// Thread = one column, 8 output rows. Streams g_h (halo rows hit L2).
// ---------------------------------------------------------------------------
__global__ void __launch_bounds__(256)
vconv_kernel()
{
    __shared__ float s_r[8];

    const int c = threadIdx.x;
    const int warp = c >> 5, lane = c & 31;
    const int img = blockIdx.x >> 5;
    const int rg = blockIdx.x & 31;            // 8-row group

    const float4* __restrict__ H = g_h + (size_t)img * (HH * WW);

    float4 a0 = {0,0,0,0}, a1 = {0,0,0,0}, a2 = {0,0,0,0}, a3 = {0,0,0,0};
    float4 a4 = {0,0,0,0}, a5 = {0,0,0,0}, a6 = {0,0,0,0}, a7 = {0,0,0,0};

    #pragma unroll
    for (int rr = 0; rr < 18; rr++) {
        const int r = (rg << 3) + rr - 5;
        float4 v = make_float4(0.f, 0.f, 0.f, 0.f);
        if ((unsigned)r < (unsigned)HH) v = H[(r << 8) + c];
        #pragma unroll
        for (int k = 0; k < 8; k++) {
            const int j = rr - k;
            if (j >= 0 && j < 11) {
                const float g = GK[j];
                float4* a = (k==0)?&a0:(k==1)?&a1:(k==2)?&a2:(k==3)?&a3:
                            (k==4)?&a4:(k==5)?&a5:(k==6)?&a6:&a7;
                a->x += g * v.x;
                a->y += g * v.y;
                a->z += g * v.z;
                a->w += g * v.w;
            }
        }
    }

    float sds = 0.f;
    #pragma unroll
    for (int k = 0; k < 8; k++) {
        const float4 a = (k==0)?a0:(k==1)?a1:(k==2)?a2:(k==3)?a3:
                         (k==4)?a4:(k==5)?a5:(k==6)?a6:a7;
        const float mx = a.x, my = a.y;
        const float mx2my2 = mx * mx + my * my;
        const float sxsy = a.z - mx2my2;       // sigma_x + sigma_y
        const float sxy = a.w - mx * my;       // sigma_xy
        const float num = (2.f * mx * my + C1S) * (2.f * sxy + C2S);
        const float den = (mx2my2 + C1S) * (sxsy + C2S) + 1e-8f;
        sds += (1.f - __fdividef(num, den));
    }
    float acc = 5.f * sds;                     // 10 * (1-ssim)/2

    #pragma unroll
    for (int o = 16; o > 0; o >>= 1)
        acc += __shfl_down_sync(0xffffffffu, acc, o);
    if (lane == 0) s_r[warp] = acc;
    __syncthreads();
    if (warp == 0) {
        float v = (lane < 8) ? s_r[lane] : 0.f;
        #pragma unroll
        for (int o = 4; o > 0; o >>= 1)
            v += __shfl_down_sync(0xffffffffu, v, o);
        if (lane == 0) g_partB[blockIdx.x] = v;
    }
}

// ---------------------------------------------------------------------------
// Final deterministic reduction (double precision, fixed order).
// ---------------------------------------------------------------------------
__global__ void __launch_bounds__(256) reduce_kernel(float* __restrict__ out)
{
    __shared__ double sd[256];
    const int tid = threadIdx.x;
    double s = 0.0;
    for (int i = tid; i < K1_BLOCKS; i += 256) s += (double)g_partA[i];
    for (int i = tid; i < K2_BLOCKS; i += 256) s += (double)g_partB[i];
    sd[tid] = s;
    __syncthreads();
    for (int st = 128; st > 0; st >>= 1) {
        if (tid < st) sd[tid] += sd[tid + st];
        __syncthreads();
    }
    if (tid == 0) {
        out[0] = (float)(sd[0] / ((double)NB * (double)NC * (double)HH * (double)WW));
    }
}

extern "C" void kernel_launch(void* const* d_in, const int* in_sizes, int n_in,
                              void* d_out, int out_size)
{
    const float* pred = (const float*)d_in[0];
    const float* targ = (const float*)d_in[1];
    const float* lm   = (const float*)d_in[2];
    float* out = (float*)d_out;
    (void)in_sizes; (void)n_in; (void)out_size;

    edge_kernel<<<NB, 256>>>(lm);
    hconv_kernel<<<K1_BLOCKS, 256>>>(pred, targ);
    vconv_kernel<<<K2_BLOCKS, 256>>>();
    reduce_kernel<<<1, 256>>>(out);
}

// round 11
// speedup vs baseline: 1.2178x; 1.1886x over previous
#include <cuda_runtime.h>
#include <cuda_bf16.h>
#include <math.h>
#include <stdint.h>

#define NB 48
#define NC 3
#define HH 256
#define WW 256
#define NIMG (NB * NC)            // 144
#define NPIX ((size_t)NIMG * HH * WW)

#define K1_BLOCKS (NIMG * 64)     // 4 rows x 64 quads per 256-thr block
#define K2_BLOCKS (NIMG * 32)     // 8 rows x 256 cols per 256-thr block

#define C1S 1e-4f
#define C2S 9e-4f

// 1D Gaussian (k=11, sigma=1.5) — compile-time constants -> FFMA-imm.
__device__ static constexpr float GK[11] = {
    0.00102840f, 0.00759880f, 0.03600060f, 0.10936270f, 0.21300441f,
    0.26601031f,
    0.21300441f, 0.10936270f, 0.03600060f, 0.00759880f, 0.00102840f
};

__device__ float g_edge[NB * HH * 24];   // per-(n,row,edge) crossing-x
__device__ float g_bbox[NB * 8];         // per-n: bx0[3], bx1[3]
__device__ uint2 g_h[NPIX];              // 4 moment fields as 2x bf16x2 (75 MB)
__device__ float g_partA[K1_BLOCKS];
__device__ float g_partB[K2_BLOCKS];

// ---------------------------------------------------------------------------
// Kernel A: per-(n,row,edge) crossing table + x-bboxes.
// ---------------------------------------------------------------------------
__global__ void __launch_bounds__(256) edge_kernel(const float* __restrict__ lm)
{
    __shared__ float lx[24], ly[24];
    __shared__ float bx0[3], bx1[3], by0[3], by1[3];

    const int n = blockIdx.x;
    const int tid = threadIdx.x;

    if (tid < 24) {
        lx[tid] = lm[(n * 68 + 36 + tid) * 2 + 0];
        ly[tid] = lm[(n * 68 + 36 + tid) * 2 + 1];
    }
    __syncthreads();
    if (tid < 3) {
        const int b = tid * 6;
        const int np = (tid == 2) ? 12 : 6;
        float mnx = lx[b], mxx = lx[b], mny = ly[b], mxy = ly[b];
        for (int i = 1; i < np; i++) {
            mnx = fminf(mnx, lx[b + i]); mxx = fmaxf(mxx, lx[b + i]);
            mny = fminf(mny, ly[b + i]); mxy = fmaxf(mxy, ly[b + i]);
        }
        float fx0 = floorf(mnx), fx1 = floorf(mxx);
        float fy0 = floorf(mny), fy1 = floorf(mxy);
        const bool valid = (fx0 >= 0.f && fy0 >= 0.f &&
                            fx1 < (float)WW && fy1 < (float)HH);
        if (!valid) { fx0 = 1e30f; fx1 = -1e30f; fy0 = 1e30f; fy1 = -1e30f; }
        bx0[tid] = fx0; bx1[tid] = fx1; by0[tid] = fy0; by1[tid] = fy1;
    }
    __syncthreads();
    if (tid < 3) {
        g_bbox[n * 8 + tid]     = bx0[tid];
        g_bbox[n * 8 + 4 + tid] = bx1[tid];
    }

    for (int u = tid; u < HH * 24; u += 256) {
        const int row = u / 24;
        const int e = u - row * 24;
        const int p3 = (e < 6) ? 0 : (e < 12) ? 1 : 2;
        const int base = p3 * 6;
        const int np = (p3 == 2) ? 12 : 6;
        const float Y = (float)row;
        const float x1 = lx[e], y1 = ly[e];
        const int e2 = base + ((e - base + 1) % np);
        const float x2 = lx[e2], y2 = ly[e2];
        const bool strad = (y1 > Y) != (y2 > Y);
        const bool rowok = (Y >= by0[p3]) && (Y < by1[p3]);
        const float xi = (x2 - x1) * (Y - y1) / (y2 - y1 + 1e-6f) + x1;
        g_edge[(size_t)n * HH * 24 + u] = (strad && rowok) ? xi : -1e30f;
    }
}

// Padding no-ops so the profiled launch (session index 3) is hconv_kernel.
__global__ void nop_kernel() {}

// ---------------------------------------------------------------------------
// Kernel 1: horizontal 11-tap conv of the 4 moment fields + weighted L1.
// One thread = 4 output cols of one row. Intermediate packed to 2x bf16x2.
// ---------------------------------------------------------------------------
__global__ void __launch_bounds__(256, 2)
hconv_kernel(const float* __restrict__ pred, const float* __restrict__ targ)
{
    __shared__ float s_r[8];

    const int tid = threadIdx.x;
    const int warp = tid >> 5, lane = tid & 31;
    const int quad = tid & 63;                 // 64 col-quads
    const int img = blockIdx.x >> 6;
    const int row = ((blockIdx.x & 63) << 2) + (tid >> 6);
    const int n = img / NC;

    const float* __restrict__ P = pred + (size_t)img * (HH * WW) + row * WW;
    const float* __restrict__ T = targ + (size_t)img * (HH * WW) + row * WW;

    // load window: cols [4q-8, 4q+12) — 5 aligned float4s, zero OOB
    const int wb = (quad << 2) - 8;
    float p[20], t[20];
    #pragma unroll
    for (int m = 0; m < 5; m++) {
        const int gc = wb + 4 * m;
        float4 vp = make_float4(0.f, 0.f, 0.f, 0.f);
        float4 vt = make_float4(0.f, 0.f, 0.f, 0.f);
        if ((unsigned)gc < (unsigned)WW) {     // gc % 4 == 0 -> whole quad in range
            vp = *(const float4*)(P + gc);
            vt = *(const float4*)(T + gc);
        }
        p[4*m+0] = vp.x; p[4*m+1] = vp.y; p[4*m+2] = vp.z; p[4*m+3] = vp.w;
        t[4*m+0] = vt.x; t[4*m+1] = vt.y; t[4*m+2] = vt.z; t[4*m+3] = vt.w;
    }

    float s2[14], pt[14];
    #pragma unroll
    for (int u = 0; u < 14; u++) {
        s2[u] = fmaf(p[u+3], p[u+3], t[u+3] * t[u+3]);   // p^2 + t^2
        pt[u] = p[u+3] * t[u+3];
    }

    uint2* __restrict__ Hout = g_h + (size_t)img * (HH * WW) + row * WW;
    #pragma unroll
    for (int k = 0; k < 4; k++) {
        float a = 0.f, b = 0.f, c = 0.f, e = 0.f;
        #pragma unroll
        for (int j = 0; j < 11; j++) {
            const float g = GK[j];
            a += g * p[k + j + 3];
            b += g * t[k + j + 3];
            c += g * s2[k + j];
            e += g * pt[k + j];
        }
        __nv_bfloat162 hab = __floats2bfloat162_rn(a, b);
        __nv_bfloat162 hce = __floats2bfloat162_rn(c, e);
        uint2 u2;
        u2.x = reinterpret_cast<unsigned&>(hab);
        u2.y = reinterpret_cast<unsigned&>(hce);
        Hout[(quad << 2) + k] = u2;
    }

    // ---- weighted L1 for these 4 pixels ----
    float acc = 0.f;
    const float bxa0 = g_bbox[n * 8 + 0], bxa1 = g_bbox[n * 8 + 4];
    const float bxb0 = g_bbox[n * 8 + 1], bxb1 = g_bbox[n * 8 + 5];
    const float bxc0 = g_bbox[n * 8 + 2], bxc1 = g_bbox[n * 8 + 6];
    const float cf = (float)(quad << 2);       // first col
    const float cl = cf + 3.f;                 // last col
    const bool tin = (bxa0 <= cl && bxa1 > cf) ||
                     (bxb0 <= cl && bxb1 > cf) ||
                     (bxc0 <= cl && bxc1 > cf);
    if (__any_sync(0xffffffffu, tin)) {
        float sx[24];
        const float* __restrict__ E = g_edge + ((size_t)n * HH + row) * 24;
        #pragma unroll
        for (int e2 = 0; e2 < 24; e2++) sx[e2] = E[e2];
        #pragma unroll
        for (int k = 0; k < 4; k++) {
            const float ad = fabsf(p[8 + k] - t[8 + k]);
            const float X = cf + (float)k;
            float w = 1.f;
            if (X >= bxa0 && X < bxa1) {
                int par = (X < sx[0]) ^ (X < sx[1]) ^ (X < sx[2]) ^
                          (X < sx[3]) ^ (X < sx[4]) ^ (X < sx[5]);
                if (par) w += 3.f;
            }
            if (X >= bxb0 && X < bxb1) {
                int par = (X < sx[6]) ^ (X < sx[7]) ^ (X < sx[8]) ^
                          (X < sx[9]) ^ (X < sx[10]) ^ (X < sx[11]);
                if (par) w += 3.f;
            }
            if (X >= bxc0 && X < bxc1) {
                int par = (X < sx[12]) ^ (X < sx[13]) ^ (X < sx[14]) ^
                          (X < sx[15]) ^ (X < sx[16]) ^ (X < sx[17]) ^
                          (X < sx[18]) ^ (X < sx[19]) ^ (X < sx[20]) ^
                          (X < sx[21]) ^ (X < sx[22]) ^ (X < sx[23]);
                if (par) w += 2.f;
            }
            acc += (10.f + 5.f * w) * ad;
        }
    } else {
        #pragma unroll
        for (int k = 0; k < 4; k++)
            acc += 15.f * fabsf(p[8 + k] - t[8 + k]);
    }

    // deterministic block reduce
    #pragma unroll
    for (int o = 16; o > 0; o >>= 1)
        acc += __shfl_down_sync(0xffffffffu, acc, o);
    if (lane == 0) s_r[warp] = acc;
    __syncthreads();
    if (warp == 0) {
        float v = (lane < 8) ? s_r[lane] : 0.f;
        #pragma unroll
        for (int o = 4; o > 0; o >>= 1)
            v += __shfl_down_sync(0xffffffffu, v, o);
        if (lane == 0) g_partA[blockIdx.x] = v;
    }
}

// ---------------------------------------------------------------------------
// Kernel 2: vertical 11-tap conv (register-blocked 8 rows / thread) + SSIM.
// Thread = one column, 8 output rows. Streams bf16-packed g_h.
// ---------------------------------------------------------------------------
__global__ void __launch_bounds__(256)
vconv_kernel()
{
    __shared__ float s_r[8];

    const int c = threadIdx.x;
    const int warp = c >> 5, lane = c & 31;
    const int img = blockIdx.x >> 5;
    const int rg = blockIdx.x & 31;            // 8-row group

    const uint2* __restrict__ H = g_h + (size_t)img * (HH * WW);

    float4 a0 = {0,0,0,0}, a1 = {0,0,0,0}, a2 = {0,0,0,0}, a3 = {0,0,0,0};
    float4 a4 = {0,0,0,0}, a5 = {0,0,0,0}, a6 = {0,0,0,0}, a7 = {0,0,0,0};

    #pragma unroll
    for (int rr = 0; rr < 18; rr++) {
        const int r = (rg << 3) + rr - 5;
        float4 v = make_float4(0.f, 0.f, 0.f, 0.f);
        if ((unsigned)r < (unsigned)HH) {
            uint2 u2 = H[(r << 8) + c];
            const __nv_bfloat162 bab = reinterpret_cast<__nv_bfloat162&>(u2.x);
            const __nv_bfloat162 bce = reinterpret_cast<__nv_bfloat162&>(u2.y);
            const float2 fab = __bfloat1622float2(bab);
            const float2 fce = __bfloat1622float2(bce);
            v = make_float4(fab.x, fab.y, fce.x, fce.y);
        }
        #pragma unroll
        for (int k = 0; k < 8; k++) {
            const int j = rr - k;
            if (j >= 0 && j < 11) {
                const float g = GK[j];
                float4* a = (k==0)?&a0:(k==1)?&a1:(k==2)?&a2:(k==3)?&a3:
                            (k==4)?&a4:(k==5)?&a5:(k==6)?&a6:&a7;
                a->x += g * v.x;
                a->y += g * v.y;
                a->z += g * v.z;
                a->w += g * v.w;
            }
        }
    }

    float sds = 0.f;
    #pragma unroll
    for (int k = 0; k < 8; k++) {
        const float4 a = (k==0)?a0:(k==1)?a1:(k==2)?a2:(k==3)?a3:
                         (k==4)?a4:(k==5)?a5:(k==6)?a6:a7;
        const float mx = a.x, my = a.y;
        const float mx2my2 = mx * mx + my * my;
        const float sxsy = a.z - mx2my2;       // sigma_x + sigma_y
        const float sxy = a.w - mx * my;       // sigma_xy
        const float num = (2.f * mx * my + C1S) * (2.f * sxy + C2S);
        const float den = (mx2my2 + C1S) * (sxsy + C2S) + 1e-8f;
        sds += (1.f - __fdividef(num, den));
    }
    float acc = 5.f * sds;                     // 10 * (1-ssim)/2

    #pragma unroll
    for (int o = 16; o > 0; o >>= 1)
        acc += __shfl_down_sync(0xffffffffu, acc, o);
    if (lane == 0) s_r[warp] = acc;
    __syncthreads();
    if (warp == 0) {
        float v = (lane < 8) ? s_r[lane] : 0.f;
        #pragma unroll
        for (int o = 4; o > 0; o >>= 1)
            v += __shfl_down_sync(0xffffffffu, v, o);
        if (lane == 0) g_partB[blockIdx.x] = v;
    }
}

// ---------------------------------------------------------------------------
// Final deterministic reduction: 8 rotating double accumulators (fixed order,
// breaks the FP64 dependence chain that cost 21us in R10).
// ---------------------------------------------------------------------------
__global__ void __launch_bounds__(256) reduce_kernel(float* __restrict__ out)
{
    __shared__ double sd[256];
    const int tid = threadIdx.x;
    double s[8] = {0, 0, 0, 0, 0, 0, 0, 0};
    {
        int j = 0;
        for (int i = tid; i < K1_BLOCKS; i += 256) {
            s[j] += (double)g_partA[i];
            j = (j + 1) & 7;
        }
        j = 0;
        for (int i = tid; i < K2_BLOCKS; i += 256) {
            s[j] += (double)g_partB[i];
            j = (j + 1) & 7;
        }
    }
    sd[tid] = ((s[0] + s[1]) + (s[2] + s[3])) + ((s[4] + s[5]) + (s[6] + s[7]));
    __syncthreads();
    for (int st = 128; st > 0; st >>= 1) {
        if (tid < st) sd[tid] += sd[tid + st];
        __syncthreads();
    }
    if (tid == 0) {
        out[0] = (float)(sd[0] / ((double)NB * (double)NC * (double)HH * (double)WW));
    }
}

extern "C" void kernel_launch(void* const* d_in, const int* in_sizes, int n_in,
                              void* d_out, int out_size)
{
    const float* pred = (const float*)d_in[0];
    const float* targ = (const float*)d_in[1];
    const float* lm   = (const float*)d_in[2];
    float* out = (float*)d_out;
    (void)in_sizes; (void)n_in; (void)out_size;

    edge_kernel<<<NB, 256>>>(lm);
    nop_kernel<<<1, 32>>>();
    nop_kernel<<<1, 32>>>();
    hconv_kernel<<<K1_BLOCKS, 256>>>(pred, targ);
    vconv_kernel<<<K2_BLOCKS, 256>>>();
    reduce_kernel<<<1, 256>>>(out);
}

// round 12
// speedup vs baseline: 1.2476x; 1.0245x over previous
#include <cuda_runtime.h>
#include <cuda_bf16.h>
#include <math.h>
#include <stdint.h>

#define NB 48
#define NC 3
#define HH 256
#define WW 256
#define HP (HH + 10)              // padded rows in intermediate (5 top, 5 bot)
#define NIMG (NB * NC)            // 144

#define K1_BLOCKS (NIMG * 64)     // 4 rows x 64 quads per 256-thr block
#define K2_BLOCKS (NIMG * 32)     // 8 rows x 256 cols per 256-thr block

#define C1S 1e-4f
#define C2S 9e-4f

// 1D Gaussian (k=11, sigma=1.5) — compile-time constants -> FFMA-imm.
__device__ static constexpr float GK[11] = {
    0.00102840f, 0.00759880f, 0.03600060f, 0.10936270f, 0.21300441f,
    0.26601031f,
    0.21300441f, 0.10936270f, 0.03600060f, 0.00759880f, 0.00102840f
};

__device__ float g_edge[NB * HH * 24];   // per-(n,row,edge) crossing-x
__device__ float g_bbox[NB * 8];         // per-n: bx0[3], bx1[3]
// Intermediate: 2x bf16x2 per px, 5 zero pad rows top+bottom per image.
// __device__ globals are zero-initialized; pads are never written, so vconv
// needs NO row-range guards at all.
__device__ uint2 g_h[(size_t)NIMG * HP * WW];   // ~78 MB
__device__ float g_partA[K1_BLOCKS];
__device__ float g_partB[K2_BLOCKS];

// ---------------------------------------------------------------------------
// Kernel A: per-(n,row,edge) crossing table + x-bboxes.
// ---------------------------------------------------------------------------
__global__ void __launch_bounds__(256) edge_kernel(const float* __restrict__ lm)
{
    __shared__ float lx[24], ly[24];
    __shared__ float bx0[3], bx1[3], by0[3], by1[3];

    const int n = blockIdx.x;
    const int tid = threadIdx.x;

    if (tid < 24) {
        lx[tid] = lm[(n * 68 + 36 + tid) * 2 + 0];
        ly[tid] = lm[(n * 68 + 36 + tid) * 2 + 1];
    }
    __syncthreads();
    if (tid < 3) {
        const int b = tid * 6;
        const int np = (tid == 2) ? 12 : 6;
        float mnx = lx[b], mxx = lx[b], mny = ly[b], mxy = ly[b];
        for (int i = 1; i < np; i++) {
            mnx = fminf(mnx, lx[b + i]); mxx = fmaxf(mxx, lx[b + i]);
            mny = fminf(mny, ly[b + i]); mxy = fmaxf(mxy, ly[b + i]);
        }
        float fx0 = floorf(mnx), fx1 = floorf(mxx);
        float fy0 = floorf(mny), fy1 = floorf(mxy);
        const bool valid = (fx0 >= 0.f && fy0 >= 0.f &&
                            fx1 < (float)WW && fy1 < (float)HH);
        if (!valid) { fx0 = 1e30f; fx1 = -1e30f; fy0 = 1e30f; fy1 = -1e30f; }
        bx0[tid] = fx0; bx1[tid] = fx1; by0[tid] = fy0; by1[tid] = fy1;
    }
    __syncthreads();
    if (tid < 3) {
        g_bbox[n * 8 + tid]     = bx0[tid];
        g_bbox[n * 8 + 4 + tid] = bx1[tid];
    }

    for (int u = tid; u < HH * 24; u += 256) {
        const int row = u / 24;
        const int e = u - row * 24;
        const int p3 = (e < 6) ? 0 : (e < 12) ? 1 : 2;
        const int base = p3 * 6;
        const int np = (p3 == 2) ? 12 : 6;
        const float Y = (float)row;
        const float x1 = lx[e], y1 = ly[e];
        const int e2 = base + ((e - base + 1) % np);
        const float x2 = lx[e2], y2 = ly[e2];
        const bool strad = (y1 > Y) != (y2 > Y);
        const bool rowok = (Y >= by0[p3]) && (Y < by1[p3]);
        const float xi = (x2 - x1) * (Y - y1) / (y2 - y1 + 1e-6f) + x1;
        g_edge[(size_t)n * HH * 24 + u] = (strad && rowok) ? xi : -1e30f;
    }
}

// Padding no-op so the profiled launch (session index 3) is vconv_kernel.
__global__ void nop_kernel() {}

// ---------------------------------------------------------------------------
// Kernel 1: horizontal 11-tap conv of the 4 moment fields + weighted L1.
// One thread = 4 output cols of one row. Interior quads (2..61) take a
// fully unconditional load path (no SEL/MOV predication overhead).
// ---------------------------------------------------------------------------
__global__ void __launch_bounds__(256, 2)
hconv_kernel(const float* __restrict__ pred, const float* __restrict__ targ)
{
    __shared__ float s_r[8];

    const int tid = threadIdx.x;
    const int warp = tid >> 5, lane = tid & 31;
    const int quad = tid & 63;                 // 64 col-quads
    const int img = blockIdx.x >> 6;
    const int row = ((blockIdx.x & 63) << 2) + (tid >> 6);
    const int n = img / NC;

    const float* __restrict__ P = pred + (size_t)img * (HH * WW) + row * WW;
    const float* __restrict__ T = targ + (size_t)img * (HH * WW) + row * WW;

    // load window: cols [4q-8, 4q+12) — 5 aligned float4 pairs
    const int wb = (quad << 2) - 8;
    float p[20], t[20];
    if (quad >= 2 && quad <= 61) {
        #pragma unroll
        for (int m = 0; m < 5; m++) {
            const float4 vp = *(const float4*)(P + wb + 4 * m);
            const float4 vt = *(const float4*)(T + wb + 4 * m);
            p[4*m+0] = vp.x; p[4*m+1] = vp.y; p[4*m+2] = vp.z; p[4*m+3] = vp.w;
            t[4*m+0] = vt.x; t[4*m+1] = vt.y; t[4*m+2] = vt.z; t[4*m+3] = vt.w;
        }
    } else {
        #pragma unroll
        for (int m = 0; m < 5; m++) {
            const int gc = wb + 4 * m;
            float4 vp = make_float4(0.f, 0.f, 0.f, 0.f);
            float4 vt = make_float4(0.f, 0.f, 0.f, 0.f);
            if ((unsigned)gc < (unsigned)WW) {
                vp = *(const float4*)(P + gc);
                vt = *(const float4*)(T + gc);
            }
            p[4*m+0] = vp.x; p[4*m+1] = vp.y; p[4*m+2] = vp.z; p[4*m+3] = vp.w;
            t[4*m+0] = vt.x; t[4*m+1] = vt.y; t[4*m+2] = vt.z; t[4*m+3] = vt.w;
        }
    }

    float s2[14], pt[14];
    #pragma unroll
    for (int u = 0; u < 14; u++) {
        s2[u] = fmaf(p[u+3], p[u+3], t[u+3] * t[u+3]);   // p^2 + t^2
        pt[u] = p[u+3] * t[u+3];
    }

    uint2* __restrict__ Hout =
        g_h + (size_t)img * (HP * WW) + (row + 5) * WW;
    unsigned ow[8];
    #pragma unroll
    for (int k = 0; k < 4; k++) {
        float a = 0.f, b = 0.f, c = 0.f, e = 0.f;
        #pragma unroll
        for (int j = 0; j < 11; j++) {
            const float g = GK[j];
            a += g * p[k + j + 3];
            b += g * t[k + j + 3];
            c += g * s2[k + j];
            e += g * pt[k + j];
        }
        __nv_bfloat162 hab = __floats2bfloat162_rn(a, b);
        __nv_bfloat162 hce = __floats2bfloat162_rn(c, e);
        ow[2*k]   = reinterpret_cast<unsigned&>(hab);
        ow[2*k+1] = reinterpret_cast<unsigned&>(hce);
    }
    uint4* dst = (uint4*)(Hout + (quad << 2));
    dst[0] = make_uint4(ow[0], ow[1], ow[2], ow[3]);
    dst[1] = make_uint4(ow[4], ow[5], ow[6], ow[7]);

    // ---- weighted L1 for these 4 pixels ----
    float acc = 0.f;
    const float bxa0 = g_bbox[n * 8 + 0], bxa1 = g_bbox[n * 8 + 4];
    const float bxb0 = g_bbox[n * 8 + 1], bxb1 = g_bbox[n * 8 + 5];
    const float bxc0 = g_bbox[n * 8 + 2], bxc1 = g_bbox[n * 8 + 6];
    const float cf = (float)(quad << 2);
    const float cl = cf + 3.f;
    const bool tin = (bxa0 <= cl && bxa1 > cf) ||
                     (bxb0 <= cl && bxb1 > cf) ||
                     (bxc0 <= cl && bxc1 > cf);
    if (__any_sync(0xffffffffu, tin)) {
        float sx[24];
        const float* __restrict__ E = g_edge + ((size_t)n * HH + row) * 24;
        #pragma unroll
        for (int e2 = 0; e2 < 24; e2++) sx[e2] = E[e2];
        #pragma unroll
        for (int k = 0; k < 4; k++) {
            const float ad = fabsf(p[8 + k] - t[8 + k]);
            const float X = cf + (float)k;
            float w = 1.f;
            if (X >= bxa0 && X < bxa1) {
                int par = (X < sx[0]) ^ (X < sx[1]) ^ (X < sx[2]) ^
                          (X < sx[3]) ^ (X < sx[4]) ^ (X < sx[5]);
                if (par) w += 3.f;
            }
            if (X >= bxb0 && X < bxb1) {
                int par = (X < sx[6]) ^ (X < sx[7]) ^ (X < sx[8]) ^
                          (X < sx[9]) ^ (X < sx[10]) ^ (X < sx[11]);
                if (par) w += 3.f;
            }
            if (X >= bxc0 && X < bxc1) {
                int par = (X < sx[12]) ^ (X < sx[13]) ^ (X < sx[14]) ^
                          (X < sx[15]) ^ (X < sx[16]) ^ (X < sx[17]) ^
                          (X < sx[18]) ^ (X < sx[19]) ^ (X < sx[20]) ^
                          (X < sx[21]) ^ (X < sx[22]) ^ (X < sx[23]);
                if (par) w += 2.f;
            }
            acc += (10.f + 5.f * w) * ad;
        }
    } else {
        #pragma unroll
        for (int k = 0; k < 4; k++)
            acc += 15.f * fabsf(p[8 + k] - t[8 + k]);
    }

    // deterministic block reduce
    #pragma unroll
    for (int o = 16; o > 0; o >>= 1)
        acc += __shfl_down_sync(0xffffffffu, acc, o);
    if (lane == 0) s_r[warp] = acc;
    __syncthreads();
    if (warp == 0) {
        float v = (lane < 8) ? s_r[lane] : 0.f;
        #pragma unroll
        for (int o = 4; o > 0; o >>= 1)
            v += __shfl_down_sync(0xffffffffu, v, o);
        if (lane == 0) g_partA[blockIdx.x] = v;
    }
}

// ---------------------------------------------------------------------------
// Kernel 2: vertical 11-tap conv (8 rows / thread) + SSIM.
// Thanks to the zero-padded intermediate there are NO row-range guards:
// every load is unconditional for every block.
// ---------------------------------------------------------------------------
__global__ void __launch_bounds__(256)
vconv_kernel()
{
    __shared__ float s_r[8];

    const int c = threadIdx.x;
    const int warp = c >> 5, lane = c & 31;
    const int img = blockIdx.x >> 5;
    const int rg = blockIdx.x & 31;            // 8-row group

    // first input row for this group is (rg*8 - 5) -> padded index rg*8
    const uint2* __restrict__ H =
        g_h + (size_t)img * (HP * WW) + (rg << 3) * WW + c;

    float4 a0 = {0,0,0,0}, a1 = {0,0,0,0}, a2 = {0,0,0,0}, a3 = {0,0,0,0};
    float4 a4 = {0,0,0,0}, a5 = {0,0,0,0}, a6 = {0,0,0,0}, a7 = {0,0,0,0};

    #pragma unroll
    for (int rr = 0; rr < 18; rr++) {
        const uint2 u2 = H[rr * WW];
        const __nv_bfloat162 bab = reinterpret_cast<const __nv_bfloat162&>(u2.x);
        const __nv_bfloat162 bce = reinterpret_cast<const __nv_bfloat162&>(u2.y);
        const float2 fab = __bfloat1622float2(bab);
        const float2 fce = __bfloat1622float2(bce);
        const float4 v = make_float4(fab.x, fab.y, fce.x, fce.y);
        #pragma unroll
        for (int k = 0; k < 8; k++) {
            const int j = rr - k;
            if (j >= 0 && j < 11) {
                const float g = GK[j];
                float4* a = (k==0)?&a0:(k==1)?&a1:(k==2)?&a2:(k==3)?&a3:
                            (k==4)?&a4:(k==5)?&a5:(k==6)?&a6:&a7;
                a->x += g * v.x;
                a->y += g * v.y;
                a->z += g * v.z;
                a->w += g * v.w;
            }
        }
    }

    float sds = 0.f;
    #pragma unroll
    for (int k = 0; k < 8; k++) {
        const float4 a = (k==0)?a0:(k==1)?a1:(k==2)?a2:(k==3)?a3:
                         (k==4)?a4:(k==5)?a5:(k==6)?a6:a7;
        const float mx = a.x, my = a.y;
        const float mx2my2 = mx * mx + my * my;
        const float sxsy = a.z - mx2my2;       // sigma_x + sigma_y
        const float sxy = a.w - mx * my;       // sigma_xy
        const float num = (2.f * mx * my + C1S) * (2.f * sxy + C2S);
        const float den = (mx2my2 + C1S) * (sxsy + C2S) + 1e-8f;
        sds += (1.f - __fdividef(num, den));
    }
    float acc = 5.f * sds;                     // 10 * (1-ssim)/2

    #pragma unroll
    for (int o = 16; o > 0; o >>= 1)
        acc += __shfl_down_sync(0xffffffffu, acc, o);
    if (lane == 0) s_r[warp] = acc;
    __syncthreads();
    if (warp == 0) {
        float v = (lane < 8) ? s_r[lane] : 0.f;
        #pragma unroll
        for (int o = 4; o > 0; o >>= 1)
            v += __shfl_down_sync(0xffffffffu, v, o);
        if (lane == 0) g_partB[blockIdx.x] = v;
    }
}

// ---------------------------------------------------------------------------
// Final deterministic reduction: 8 rotating double accumulators.
// ---------------------------------------------------------------------------
__global__ void __launch_bounds__(256) reduce_kernel(float* __restrict__ out)
{
    __shared__ double sd[256];
    const int tid = threadIdx.x;
    double s[8] = {0, 0, 0, 0, 0, 0, 0, 0};
    {
        int j = 0;
        for (int i = tid; i < K1_BLOCKS; i += 256) {
            s[j] += (double)g_partA[i];
            j = (j + 1) & 7;
        }
        j = 0;
        for (int i = tid; i < K2_BLOCKS; i += 256) {
            s[j] += (double)g_partB[i];
            j = (j + 1) & 7;
        }
    }
    sd[tid] = ((s[0] + s[1]) + (s[2] + s[3])) + ((s[4] + s[5]) + (s[6] + s[7]));
    __syncthreads();
    for (int st = 128; st > 0; st >>= 1) {
        if (tid < st) sd[tid] += sd[tid + st];
        __syncthreads();
    }
    if (tid == 0) {
        out[0] = (float)(sd[0] / ((double)NB * (double)NC * (double)HH * (double)WW));
    }
}

extern "C" void kernel_launch(void* const* d_in, const int* in_sizes, int n_in,
                              void* d_out, int out_size)
{
    const float* pred = (const float*)d_in[0];
    const float* targ = (const float*)d_in[1];
    const float* lm   = (const float*)d_in[2];
    float* out = (float*)d_out;
    (void)in_sizes; (void)n_in; (void)out_size;

    edge_kernel<<<NB, 256>>>(lm);
    nop_kernel<<<1, 32>>>();
    hconv_kernel<<<K1_BLOCKS, 256>>>(pred, targ);
    vconv_kernel<<<K2_BLOCKS, 256>>>();
    reduce_kernel<<<1, 256>>>(out);
}